// round 10
// baseline (speedup 1.0000x reference)
#include <cuda_runtime.h>
#include <cstdint>

// Leaky RNN: x_t = 0.9*x_{t-1} + 0.1*(u@Win + tanh(x_{t-1})@Wrec + brec) + q_t
//            z_t = tanh(x_t)@Wout + bout
// T=1024, B=64, NIN=32, N=256, NOUT=16.
//
// Pre : g[t,b,n] = noise + 0.1*(u@Win + brec)
// A   : 128 CTAs = 64 batches x 2 cluster ranks (k-split halves).
//       Thread (s=tid>>6, c=tid&63): 4 cols {own c, own c+64, peer c, peer c+64}
//       over k-sub [128rho+32s, +32). 64 ull weights in regs. PEER partials are
//       computed FIRST and sent RAW (2x st.shared::cluster + arrive.release,
//       count=256) so the 215-cyc DSMEM flight overlaps own-col FMAs + local
//       reduce. Owner sums 4 inbox + 4 local partials. No sender-side reduce.
// B   : outputs = tanh(states) @ Wout + bout.

#define T_STEPS 1024
#define B_SZ    64
#define N_IN    32
#define N_HID   256
#define N_OUT   16

typedef unsigned long long ull;

__device__ float g_buf[T_STEPS * B_SZ * N_HID];

__device__ __forceinline__ void ffma2(ull& acc, ull a, ull b) {
    asm("fma.rn.f32x2 %0, %1, %2, %0;" : "+l"(acc) : "l"(a), "l"(b));
}
__device__ __forceinline__ ull pack2(float lo, float hi) {
    ull r; asm("mov.b64 %0, {%1, %2};" : "=l"(r) : "f"(lo), "f"(hi)); return r;
}
__device__ __forceinline__ float hadd2(ull a) {
    float lo, hi; asm("mov.b64 {%0, %1}, %2;" : "=f"(lo), "=f"(hi) : "l"(a));
    return lo + hi;
}
__device__ __forceinline__ float ftanh(float x) {
    float e = __expf(2.0f * x);
    return 1.0f - __fdividef(2.0f, e + 1.0f);
}
__device__ __forceinline__ unsigned mapa32(unsigned laddr, unsigned peer) {
    unsigned r;
    asm volatile("mapa.shared::cluster.u32 %0, %1, %2;" : "=r"(r) : "r"(laddr), "r"(peer));
    return r;
}
__device__ __forceinline__ void st_remote_f32(unsigned addr, float v) {
    asm volatile("st.shared::cluster.f32 [%0], %1;" :: "r"(addr), "f"(v) : "memory");
}
__device__ __forceinline__ void arrive_remote(unsigned addr) {
    asm volatile("mbarrier.arrive.release.cluster.shared::cluster.b64 _, [%0];"
                 :: "r"(addr) : "memory");
}
__device__ __forceinline__ void mbar_wait_cluster(unsigned addr, unsigned parity) {
    unsigned done;
    do {
        asm volatile(
            "{\n\t.reg .pred P;\n\t"
            "mbarrier.try_wait.parity.acquire.cluster.shared::cta.b64 P, [%1], %2, 0x989680;\n\t"
            "selp.b32 %0, 1, 0, P;\n\t}"
            : "=r"(done) : "r"(addr), "r"(parity) : "memory");
    } while (!done);
}
#define CLUSTER_SYNC() do { \
    asm volatile("barrier.cluster.arrive.aligned;" ::: "memory"); \
    asm volatile("barrier.cluster.wait.aligned;"   ::: "memory"); } while (0)

// ---------------- Pre-kernel: g = noise + 0.1*(u@Win + brec) ----------------
__global__ void __launch_bounds__(256)
uproj_kernel(const float* __restrict__ inputs,   // [T*B, NIN]
             const float* __restrict__ noise,    // [T*B, N]
             const float* __restrict__ Win,      // [NIN, N]
             const float* __restrict__ brec)     // [N]
{
    __shared__ float su[8][N_IN];
    const int tid = threadIdx.x;

    float w_in[N_IN];
#pragma unroll
    for (int i = 0; i < N_IN; ++i) w_in[i] = Win[i * N_HID + tid];
    const float br = brec[tid];

    const int row0 = blockIdx.x * 8;
    su[tid >> 5][tid & 31] = inputs[row0 * N_IN + tid];
    __syncthreads();

#pragma unroll
    for (int rr = 0; rr < 8; ++rr) {
        const int row = row0 + rr;
        float acc = br;
#pragma unroll
        for (int i = 0; i < N_IN; ++i) acc = fmaf(su[rr][i], w_in[i], acc);
        g_buf[row * N_HID + tid] = noise[row * N_HID + tid] + 0.1f * acc;
    }
}

// ---------------- Kernel A: recurrence (direct partial exchange) ----------------
__global__ void __launch_bounds__(256, 1) __cluster_dims__(2, 1, 1)
rnn_step_kernel(const float* __restrict__ x0,     // [B,N]
                const float* __restrict__ Wrec,   // [N,N]
                float* __restrict__ states)       // [T,B,N]
{
    __shared__ __align__(16) float r_s[2][128];      // own-half r, dbl-buffered
    __shared__ __align__(16) float sRed[4][128];     // own-col partials [s][li]
    __shared__ __align__(16) float inbox[2][4][128]; // raw peer partials [p][s][li]
    __shared__ __align__(8)  ull   mbar[2];

    const int tid = threadIdx.x;
    const int b   = blockIdx.x >> 1;
    const unsigned rho = blockIdx.x & 1u;
    const int s   = tid >> 6;            // k sub-slice 0..3 (32 k each)
    const int c   = tid & 63;
    const int k0  = (int)rho * 128 + 32 * s;

    const int ownBase  = (int)rho * 128;
    const int peerBase = ((int)rho ^ 1) * 128;

    // weights (64 ull): own cols c, c+64 and peer cols c, c+64, over own k-sub
    ull WO0[16], WO1[16], WP0[16], WP1[16];
#pragma unroll
    for (int i = 0; i < 16; ++i) {
        const int k = k0 + 2 * i;
        WO0[i] = pack2(Wrec[k * N_HID + ownBase + c],
                       Wrec[(k + 1) * N_HID + ownBase + c]);
        WO1[i] = pack2(Wrec[k * N_HID + ownBase + c + 64],
                       Wrec[(k + 1) * N_HID + ownBase + c + 64]);
        WP0[i] = pack2(Wrec[k * N_HID + peerBase + c],
                       Wrec[(k + 1) * N_HID + peerBase + c]);
        WP1[i] = pack2(Wrec[k * N_HID + peerBase + c + 64],
                       Wrec[(k + 1) * N_HID + peerBase + c + 64]);
    }

    if (tid == 0) {
        asm volatile("mbarrier.init.shared.b64 [%0], %1;"
                     :: "r"((unsigned)__cvta_generic_to_shared(&mbar[0])), "r"(256) : "memory");
        asm volatile("mbarrier.init.shared.b64 [%0], %1;"
                     :: "r"((unsigned)__cvta_generic_to_shared(&mbar[1])), "r"(256) : "memory");
    }

    // remote addresses: inbox[0][s][c] on peer CTA, and peer's mbar
    unsigned l_in = (unsigned)__cvta_generic_to_shared(&inbox[0][s][c]);
    const unsigned r_inbox = mapa32(l_in, rho ^ 1u);
    const unsigned r_mbar  = mapa32((unsigned)__cvta_generic_to_shared(&mbar[0]), rho ^ 1u);

    float x = 0.0f, greg = 0.0f;
    const float* gp = g_buf + b * N_HID + ownBase + tid;   // owner col (tid<128)
    float* sp = states + b * N_HID + ownBase + tid;

    if (tid < 128) {
        x = x0[b * N_HID + ownBase + tid];
        r_s[0][tid] = ftanh(x);
        greg = gp[0];
    }

    __syncthreads();
    CLUSTER_SYNC();                       // peer mbar init visible

    const unsigned mb0 = (unsigned)__cvta_generic_to_shared(&mbar[0]);
    int ph0 = 0, ph1 = 0;

#pragma unroll 1
    for (int t = 0; t < T_STEPS; ++t) {
        const int p    = t & 1;
        const int nbuf = p ^ 1;

        // ---- load own 32-float r sub-slice (8 broadcast LDS.128) ----
        const ulonglong2* rp = reinterpret_cast<const ulonglong2*>(&r_s[p][32 * s]);
        ulonglong2 rv[8];
#pragma unroll
        for (int q = 0; q < 8; ++q) rv[q] = rp[q];

        // ---- PEER columns first: 32 FFMA2, then ship raw partials ----
        ull b0 = 0, b1 = 0;
#pragma unroll
        for (int q = 0; q < 8; ++q) {
            ffma2(b0, WP0[2 * q], rv[q].x);  ffma2(b0, WP0[2 * q + 1], rv[q].y);
            ffma2(b1, WP1[2 * q], rv[q].x);  ffma2(b1, WP1[2 * q + 1], rv[q].y);
        }
        {
            const unsigned dst = r_inbox + (unsigned)(p * 2048);
            st_remote_f32(dst,       hadd2(b0));
            st_remote_f32(dst + 256, hadd2(b1));          // col c+64 = +64 floats
            arrive_remote(r_mbar + (unsigned)(p * 8));    // release orders both
        }

        // ---- OWN columns: 32 FFMA2 (overlaps remote flight) ----
        ull a0 = 0, a1 = 0;
#pragma unroll
        for (int q = 0; q < 8; ++q) {
            ffma2(a0, WO0[2 * q], rv[q].x);  ffma2(a0, WO0[2 * q + 1], rv[q].y);
            ffma2(a1, WO1[2 * q], rv[q].x);  ffma2(a1, WO1[2 * q + 1], rv[q].y);
        }
        sRed[s][c]      = hadd2(a0);
        sRed[s][c + 64] = hadd2(a1);

        __syncthreads();                  // local partials visible

        if (tid < 128) {
            const int tq = (t + 1 < T_STEPS) ? (t + 1) : (T_STEPS - 1);
            const float gnext = gp[tq * (B_SZ * N_HID)];  // prefetch g_{t+1}

            const float own = (sRed[0][tid] + sRed[1][tid])
                            + (sRed[2][tid] + sRed[3][tid]);

            if (p == 0) { mbar_wait_cluster(mb0, ph0); ph0 ^= 1; }
            else        { mbar_wait_cluster(mb0 + 8, ph1); ph1 ^= 1; }

            const float pin = (inbox[p][0][tid] + inbox[p][1][tid])
                            + (inbox[p][2][tid] + inbox[p][3][tid]);

            x = 0.9f * x + 0.1f * (own + pin) + greg;
            greg = gnext;
            r_s[nbuf][tid] = ftanh(x);
            sp[t * (B_SZ * N_HID)] = x;   // fire-and-forget
        }

        __syncthreads();                  // r_s[nbuf] ready; sRed reusable
    }

    CLUSTER_SYNC();                       // smem alive until peer traffic lands
}

// ---------------- Kernel B: z = tanh(states) @ Wout + bout ----------------
__global__ void __launch_bounds__(256, 1)
rnn_out_kernel(const float* __restrict__ states,  // [T*B, N]
               const float* __restrict__ Wout,    // [N, NOUT]
               const float* __restrict__ bout,    // [NOUT]
               float* __restrict__ outputs)       // [T*B, NOUT]
{
    __shared__ __align__(16) float srow[8][N_HID];

    const int tid  = threadIdx.x;
    const int wid  = tid >> 5;
    const int lane = tid & 31;
    const int o    = lane & 15;
    const int h    = lane >> 4;

    ull w[64];
#pragma unroll
    for (int j = 0; j < 64; ++j) {
        int nn = h * 128 + 2 * j;
        w[j] = pack2(Wout[nn * N_OUT + o], Wout[(nn + 1) * N_OUT + o]);
    }
    const float bo = bout[o];

    const int rows = T_STEPS * B_SZ;
    const int warps_total = (gridDim.x * blockDim.x) >> 5;
    int row = (blockIdx.x * blockDim.x + tid) >> 5;
    if (row >= rows) return;

    const float4* src = reinterpret_cast<const float4*>(states + (size_t)row * N_HID);
    float4 v0 = src[lane];
    float4 v1 = src[32 + lane];

    while (true) {
        const int nrow = row + warps_total;
        float4 n0, n1;
        if (nrow < rows) {
            const float4* nsrc = reinterpret_cast<const float4*>(states + (size_t)nrow * N_HID);
            n0 = nsrc[lane];
            n1 = nsrc[32 + lane];
        }

        v0.x = ftanh(v0.x); v0.y = ftanh(v0.y); v0.z = ftanh(v0.z); v0.w = ftanh(v0.w);
        v1.x = ftanh(v1.x); v1.y = ftanh(v1.y); v1.z = ftanh(v1.z); v1.w = ftanh(v1.w);
        float4* dst = reinterpret_cast<float4*>(&srow[wid][0]);
        dst[lane]      = v0;
        dst[32 + lane] = v1;
        __syncwarp();

        const ulonglong2* rp = reinterpret_cast<const ulonglong2*>(&srow[wid][h << 7]);
        ull a0 = 0, a1 = 0;
#pragma unroll
        for (int gq = 0; gq < 32; ++gq) {
            ulonglong2 q = rp[gq];
            ffma2(a0, w[2 * gq + 0], q.x);
            ffma2(a1, w[2 * gq + 1], q.y);
        }
        float zz = hadd2(a0) + hadd2(a1);
        zz += __shfl_xor_sync(0xffffffffu, zz, 16);
        if (h == 0)
            outputs[(size_t)row * N_OUT + o] = zz + bo;
        __syncwarp();

        if (nrow >= rows) break;
        row = nrow; v0 = n0; v1 = n1;
    }
}

extern "C" void kernel_launch(void* const* d_in, const int* in_sizes, int n_in,
                              void* d_out, int out_size) {
    const float* inputs = (const float*)d_in[0];
    const float* noise  = (const float*)d_in[1];
    const float* x0     = (const float*)d_in[2];
    const float* Win    = (const float*)d_in[3];
    const float* Wrec   = (const float*)d_in[4];
    const float* brec   = (const float*)d_in[5];
    const float* Wout   = (const float*)d_in[6];
    const float* bout   = (const float*)d_in[7];

    float* outputs = (float*)d_out;                                  // [T,B,NOUT]
    float* states  = (float*)d_out + (size_t)T_STEPS * B_SZ * N_OUT; // [T,B,N]

    uproj_kernel<<<dim3(T_STEPS * B_SZ / 8), dim3(256)>>>(inputs, noise, Win, brec);
    rnn_step_kernel<<<dim3(B_SZ * 2), dim3(256)>>>(x0, Wrec, states);
    rnn_out_kernel<<<dim3(592), dim3(256)>>>(states, Wout, bout, outputs);
}

// round 11
// speedup vs baseline: 1.0174x; 1.0174x over previous
#include <cuda_runtime.h>
#include <cstdint>

// Leaky RNN: x_t = 0.9*x_{t-1} + 0.1*(u@Win + tanh(x_{t-1})@Wrec + brec) + q_t
//            z_t = tanh(x_t)@Wout + bout
// T=1024, B=64, NIN=32, N=256, NOUT=16.
//
// Pre : g[t,b,n] = noise + 0.1*(u@Win + brec)
// A   : 128 CTAs = 64 batches x 2 cluster ranks. CTA owns 128 cols, computes
//       FULL 256-k dots for them. r-halves are exchanged (warp 4 ships the
//       local 128-float r-half as 32 x st.shared::cluster.v4 + 32 arrives).
//       Warps 0-3 dot own k-half (local r, no wait); warps 4-7 wait mbar then
//       dot the peer k-half from the inbox. Owners (tid<128) sum 8 partials.
// B   : outputs = tanh(states) @ Wout + bout.

#define T_STEPS 1024
#define B_SZ    64
#define N_IN    32
#define N_HID   256
#define N_OUT   16

typedef unsigned long long ull;

__device__ float g_buf[T_STEPS * B_SZ * N_HID];

__device__ __forceinline__ void ffma2(ull& acc, ull a, ull b) {
    asm("fma.rn.f32x2 %0, %1, %2, %0;" : "+l"(acc) : "l"(a), "l"(b));
}
__device__ __forceinline__ ull pack2(float lo, float hi) {
    ull r; asm("mov.b64 %0, {%1, %2};" : "=l"(r) : "f"(lo), "f"(hi)); return r;
}
__device__ __forceinline__ float hadd2(ull a) {
    float lo, hi; asm("mov.b64 {%0, %1}, %2;" : "=f"(lo), "=f"(hi) : "l"(a));
    return lo + hi;
}
__device__ __forceinline__ float ftanh(float x) {
    float e = __expf(2.0f * x);
    return 1.0f - __fdividef(2.0f, e + 1.0f);
}
__device__ __forceinline__ unsigned mapa32(unsigned laddr, unsigned peer) {
    unsigned r;
    asm volatile("mapa.shared::cluster.u32 %0, %1, %2;" : "=r"(r) : "r"(laddr), "r"(peer));
    return r;
}
__device__ __forceinline__ void st_remote_v4(unsigned addr, float4 v) {
    asm volatile("st.shared::cluster.v4.f32 [%0], {%1, %2, %3, %4};"
                 :: "r"(addr), "f"(v.x), "f"(v.y), "f"(v.z), "f"(v.w) : "memory");
}
__device__ __forceinline__ void arrive_remote(unsigned addr) {
    asm volatile("mbarrier.arrive.release.cluster.shared::cluster.b64 _, [%0];"
                 :: "r"(addr) : "memory");
}
__device__ __forceinline__ void mbar_wait_cluster(unsigned addr, unsigned parity) {
    unsigned done;
    do {
        asm volatile(
            "{\n\t.reg .pred P;\n\t"
            "mbarrier.try_wait.parity.acquire.cluster.shared::cta.b64 P, [%1], %2, 0x989680;\n\t"
            "selp.b32 %0, 1, 0, P;\n\t}"
            : "=r"(done) : "r"(addr), "r"(parity) : "memory");
    } while (!done);
}
#define CLUSTER_SYNC() do { \
    asm volatile("barrier.cluster.arrive.aligned;" ::: "memory"); \
    asm volatile("barrier.cluster.wait.aligned;"   ::: "memory"); } while (0)

// ---------------- Pre-kernel: g = noise + 0.1*(u@Win + brec) ----------------
__global__ void __launch_bounds__(256)
uproj_kernel(const float* __restrict__ inputs,   // [T*B, NIN]
             const float* __restrict__ noise,    // [T*B, N]
             const float* __restrict__ Win,      // [NIN, N]
             const float* __restrict__ brec)     // [N]
{
    __shared__ float su[8][N_IN];
    const int tid = threadIdx.x;

    float w_in[N_IN];
#pragma unroll
    for (int i = 0; i < N_IN; ++i) w_in[i] = Win[i * N_HID + tid];
    const float br = brec[tid];

    const int row0 = blockIdx.x * 8;
    su[tid >> 5][tid & 31] = inputs[row0 * N_IN + tid];
    __syncthreads();

#pragma unroll
    for (int rr = 0; rr < 8; ++rr) {
        const int row = row0 + rr;
        float acc = br;
#pragma unroll
        for (int i = 0; i < N_IN; ++i) acc = fmaf(su[rr][i], w_in[i], acc);
        g_buf[row * N_HID + tid] = noise[row * N_HID + tid] + 0.1f * acc;
    }
}

// ---------------- Kernel A: recurrence (r-half exchange, full own-col dots) ----------------
__global__ void __launch_bounds__(256, 1) __cluster_dims__(2, 1, 1)
rnn_step_kernel(const float* __restrict__ x0,     // [B,N]
                const float* __restrict__ Wrec,   // [N,N]
                float* __restrict__ states)       // [T,B,N]
{
    __shared__ __align__(16) float r_s[2][128];    // own-half r, dbl-buffered
    __shared__ __align__(16) float inbox[2][128];  // peer r-half, dbl-buffered
    __shared__ __align__(16) float sRed[8][128];   // partials [s][local col]
    __shared__ __align__(8)  ull   mbar[2];

    const int tid = threadIdx.x;
    const int b   = blockIdx.x >> 1;
    const unsigned rho = blockIdx.x & 1u;
    const int s   = tid >> 5;            // k sub-slice 0..7 (32 k each)
    const int c   = tid & 31;            // column sub-index

    const int ownBase  = (int)rho * 128;
    const int peerBase = ((int)rho ^ 1) * 128;
    // sub-slice k base: s<4 -> own k-half (local r); s>=4 -> peer k-half (inbox)
    const int kbase = (s < 4) ? (ownBase + 32 * s) : (peerBase + 32 * (s - 4));

    // weights: W[j][i] = (Wrec[kbase+2i][ownBase+c+32j], Wrec[kbase+2i+1][...]), 64 ull
    ull W0[16], W1[16], W2[16], W3[16];
#pragma unroll
    for (int i = 0; i < 16; ++i) {
        const int k = kbase + 2 * i;
        const int cb = ownBase + c;
        W0[i] = pack2(Wrec[k * N_HID + cb],       Wrec[(k + 1) * N_HID + cb]);
        W1[i] = pack2(Wrec[k * N_HID + cb + 32],  Wrec[(k + 1) * N_HID + cb + 32]);
        W2[i] = pack2(Wrec[k * N_HID + cb + 64],  Wrec[(k + 1) * N_HID + cb + 64]);
        W3[i] = pack2(Wrec[k * N_HID + cb + 96],  Wrec[(k + 1) * N_HID + cb + 96]);
    }

    if (tid == 0) {
        asm volatile("mbarrier.init.shared.b64 [%0], %1;"
                     :: "r"((unsigned)__cvta_generic_to_shared(&mbar[0])), "r"(32) : "memory");
        asm volatile("mbarrier.init.shared.b64 [%0], %1;"
                     :: "r"((unsigned)__cvta_generic_to_shared(&mbar[1])), "r"(32) : "memory");
    }

    // warp 4 sender addresses: peer inbox[0][4c] and peer mbar
    const unsigned r_inbox = mapa32(
        (unsigned)__cvta_generic_to_shared(&inbox[0][4 * c]), rho ^ 1u);
    const unsigned r_mbar = mapa32(
        (unsigned)__cvta_generic_to_shared(&mbar[0]), rho ^ 1u);

    float x = 0.0f, greg = 0.0f;
    const float* gp = g_buf + b * N_HID + ownBase + tid;    // owner col (tid<128)
    float* sp = states + b * N_HID + ownBase + tid;

    if (tid < 128) {
        x = x0[b * N_HID + ownBase + tid];
        r_s[0][tid] = ftanh(x);          // r_{-1}, own half
        greg = gp[0];
    }

    __syncthreads();
    CLUSTER_SYNC();                      // peer mbar init visible

    const unsigned mb0 = (unsigned)__cvta_generic_to_shared(&mbar[0]);
    int ph0 = 0, ph1 = 0;

#pragma unroll 1
    for (int t = 0; t < T_STEPS; ++t) {
        const int p    = t & 1;
        const int nbuf = p ^ 1;

        // ---- warp 4: ship local r-half (r_{t-1}) to peer inbox[p] ----
        if (s == 4) {
            const float4 rv4 = *reinterpret_cast<const float4*>(&r_s[p][4 * c]);
            st_remote_v4(r_inbox + (unsigned)(p * 512), rv4);
            arrive_remote(r_mbar + (unsigned)(p * 8));   // release orders the v4
        }

        // ---- select r source; warps 4-7 wait for peer half ----
        const float* rsrc;
        if (s < 4) {
            rsrc = &r_s[p][32 * s];
        } else {
            if (p == 0) { if (s == 4 ? true : true) {} }
            if (s >= 4) {
                if (p == 0) { mbar_wait_cluster(mb0, ph0); ph0 ^= 1; }
                else        { mbar_wait_cluster(mb0 + 8, ph1); ph1 ^= 1; }
            }
            rsrc = &inbox[p][32 * (s - 4)];
        }

        // ---- dot: 8 broadcast LDS.128 + 64 FFMA2 for 4 columns ----
        const ulonglong2* rp = reinterpret_cast<const ulonglong2*>(rsrc);
        ulonglong2 rv[8];
#pragma unroll
        for (int q = 0; q < 8; ++q) rv[q] = rp[q];

        ull a0 = 0, a1 = 0, a2 = 0, a3 = 0;
#pragma unroll
        for (int q = 0; q < 8; ++q) {
            ffma2(a0, W0[2 * q], rv[q].x);  ffma2(a0, W0[2 * q + 1], rv[q].y);
            ffma2(a1, W1[2 * q], rv[q].x);  ffma2(a1, W1[2 * q + 1], rv[q].y);
            ffma2(a2, W2[2 * q], rv[q].x);  ffma2(a2, W2[2 * q + 1], rv[q].y);
            ffma2(a3, W3[2 * q], rv[q].x);  ffma2(a3, W3[2 * q + 1], rv[q].y);
        }
        sRed[s][c]      = hadd2(a0);
        sRed[s][c + 32] = hadd2(a1);
        sRed[s][c + 64] = hadd2(a2);
        sRed[s][c + 96] = hadd2(a3);

        __syncthreads();                 // all 8 partial rows visible

        if (tid < 128) {
            const int tq = (t + 1 < T_STEPS) ? (t + 1) : (T_STEPS - 1);
            const float gnext = gp[tq * (B_SZ * N_HID)];

            const float tot = ((sRed[0][tid] + sRed[1][tid])
                             + (sRed[2][tid] + sRed[3][tid]))
                            + ((sRed[4][tid] + sRed[5][tid])
                             + (sRed[6][tid] + sRed[7][tid]));

            x = 0.9f * x + 0.1f * tot + greg;
            greg = gnext;
            r_s[nbuf][tid] = ftanh(x);
            sp[t * (B_SZ * N_HID)] = x;  // fire-and-forget
        }

        __syncthreads();                 // r_s[nbuf] ready; sRed reusable
    }

    CLUSTER_SYNC();                      // smem alive until peer traffic lands
}

// ---------------- Kernel B: z = tanh(states) @ Wout + bout ----------------
__global__ void __launch_bounds__(256, 1)
rnn_out_kernel(const float* __restrict__ states,  // [T*B, N]
               const float* __restrict__ Wout,    // [N, NOUT]
               const float* __restrict__ bout,    // [NOUT]
               float* __restrict__ outputs)       // [T*B, NOUT]
{
    __shared__ __align__(16) float srow[8][N_HID];

    const int tid  = threadIdx.x;
    const int wid  = tid >> 5;
    const int lane = tid & 31;
    const int o    = lane & 15;
    const int h    = lane >> 4;

    ull w[64];
#pragma unroll
    for (int j = 0; j < 64; ++j) {
        int nn = h * 128 + 2 * j;
        w[j] = pack2(Wout[nn * N_OUT + o], Wout[(nn + 1) * N_OUT + o]);
    }
    const float bo = bout[o];

    const int rows = T_STEPS * B_SZ;
    const int warps_total = (gridDim.x * blockDim.x) >> 5;
    int row = (blockIdx.x * blockDim.x + tid) >> 5;
    if (row >= rows) return;

    const float4* src = reinterpret_cast<const float4*>(states + (size_t)row * N_HID);
    float4 v0 = src[lane];
    float4 v1 = src[32 + lane];

    while (true) {
        const int nrow = row + warps_total;
        float4 n0, n1;
        if (nrow < rows) {
            const float4* nsrc = reinterpret_cast<const float4*>(states + (size_t)nrow * N_HID);
            n0 = nsrc[lane];
            n1 = nsrc[32 + lane];
        }

        v0.x = ftanh(v0.x); v0.y = ftanh(v0.y); v0.z = ftanh(v0.z); v0.w = ftanh(v0.w);
        v1.x = ftanh(v1.x); v1.y = ftanh(v1.y); v1.z = ftanh(v1.z); v1.w = ftanh(v1.w);
        float4* dst = reinterpret_cast<float4*>(&srow[wid][0]);
        dst[lane]      = v0;
        dst[32 + lane] = v1;
        __syncwarp();

        const ulonglong2* rp = reinterpret_cast<const ulonglong2*>(&srow[wid][h << 7]);
        ull a0 = 0, a1 = 0;
#pragma unroll
        for (int gq = 0; gq < 32; ++gq) {
            ulonglong2 q = rp[gq];
            ffma2(a0, w[2 * gq + 0], q.x);
            ffma2(a1, w[2 * gq + 1], q.y);
        }
        float zz = hadd2(a0) + hadd2(a1);
        zz += __shfl_xor_sync(0xffffffffu, zz, 16);
        if (h == 0)
            outputs[(size_t)row * N_OUT + o] = zz + bo;
        __syncwarp();

        if (nrow >= rows) break;
        row = nrow; v0 = n0; v1 = n1;
    }
}

extern "C" void kernel_launch(void* const* d_in, const int* in_sizes, int n_in,
                              void* d_out, int out_size) {
    const float* inputs = (const float*)d_in[0];
    const float* noise  = (const float*)d_in[1];
    const float* x0     = (const float*)d_in[2];
    const float* Win    = (const float*)d_in[3];
    const float* Wrec   = (const float*)d_in[4];
    const float* brec   = (const float*)d_in[5];
    const float* Wout   = (const float*)d_in[6];
    const float* bout   = (const float*)d_in[7];

    float* outputs = (float*)d_out;                                  // [T,B,NOUT]
    float* states  = (float*)d_out + (size_t)T_STEPS * B_SZ * N_OUT; // [T,B,N]

    uproj_kernel<<<dim3(T_STEPS * B_SZ / 8), dim3(256)>>>(inputs, noise, Win, brec);
    rnn_step_kernel<<<dim3(B_SZ * 2), dim3(256)>>>(x0, Wrec, states);
    rnn_out_kernel<<<dim3(592), dim3(256)>>>(states, Wout, bout, outputs);
}